// round 16
// baseline (speedup 1.0000x reference)
#include <cuda_runtime.h>
#include <cuda_fp16.h>
#include <stdint.h>

#define N_NODES  50000
#define N_EDGES  800000
#define IN_F     128
#define OUT_F    128

#define SCAN_T   256
#define SCAN_B   ((N_NODES + SCAN_T - 1) / SCAN_T)   // 196

#define NUM_SM   148
#define TILE_M   128
#define N_TILES  ((N_NODES + TILE_M - 1) / TILE_M)   // 391

#define W_PAD    136   // W smem row stride in halves (bank-conflict-free)

#define BUILD_B  782   // build kernel blocks (= fill shape; 782*256 = 200192)

// -------------------- device scratch (no allocation allowed) ---------------
__device__ __align__(16) __half g_xh[N_NODES * IN_F];    // fp16 copy of x
__device__ __align__(16) __half g_aggh[N_NODES * IN_F];  // fp16 normalized h
__device__ __align__(16) __half g_wh[OUT_F * IN_F];      // fp16 copy of W
__device__ int   g_cnt4[4 * N_NODES];   // replicated histograms (stripe = edge%4)
__device__ int   g_base4[4 * N_NODES];  // per-(node,replica) bases; row0 = CSR start
__device__ int   g_cnt[N_NODES];        // per-node totals
__device__ __align__(16) int g_rank[N_EDGES];  // rank within (node,replica)
__device__ int   g_srcs[N_EDGES];       // edge sources grouped by dst
__device__ int   g_bsums[SCAN_B];
__device__ int   g_barrier;             // monotonic; reset by agg_kernel (next in stream)

// -------------------- grid barrier (all BUILD_B blocks resident) -----------
__device__ __forceinline__ void grid_barrier(int target) {
    __syncthreads();
    if (threadIdx.x == 0) {
        __threadfence();
        atomicAdd(&g_barrier, 1);
        int v;
        do {
            asm volatile("ld.global.acquire.gpu.b32 %0, [%1];"
                         : "=r"(v) : "l"(&g_barrier));
        } while (v < target);
    }
    __syncthreads();
}

// -------------------- fused build: convert -> hist -> scan -> fill ---------
__global__ void __launch_bounds__(256, 6)
build_kernel(const float4* __restrict__ x4, const float* __restrict__ W,
             const int* __restrict__ ei) {
    __shared__ int st[SCAN_T];
    __shared__ int sb[SCAN_T];

    const int tid  = threadIdx.x;
    const int gtid = blockIdx.x * 256 + tid;           // 0 .. 200191
    const int stride = BUILD_B * 256;                  // 200192

    // ---- P0: convert x->fp16, W->fp16, zero g_cnt4 ----
    {
        uint2* xh2 = reinterpret_cast<uint2*>(g_xh);
        const int n4 = N_NODES * IN_F / 4;   // 1.6M -> 8 iters/thread
        for (int i = gtid; i < n4; i += stride) {
            float4 v = x4[i];
            __half2 h0 = __floats2half2_rn(v.x, v.y);
            __half2 h1 = __floats2half2_rn(v.z, v.w);
            uint2 p;
            p.x = *reinterpret_cast<unsigned*>(&h0);
            p.y = *reinterpret_cast<unsigned*>(&h1);
            xh2[i] = p;
        }
        unsigned* wh2 = reinterpret_cast<unsigned*>(g_wh);
        if (gtid < OUT_F * IN_F / 2) {
            float2 w = reinterpret_cast<const float2*>(W)[gtid];
            __half2 h = __floats2half2_rn(w.x, w.y);
            wh2[gtid] = *reinterpret_cast<unsigned*>(&h);
        }
        int4* cnt4v = reinterpret_cast<int4*>(g_cnt4);
        if (gtid < N_NODES) cnt4v[gtid] = make_int4(0, 0, 0, 0);
    }
    grid_barrier(1 * BUILD_B);

    // ---- P1: histogram (replicated) + rank capture ----
    const int e4 = gtid;
    const bool has_e = (e4 < N_EDGES / 4);
    int4 es, ed;
    if (has_e) {
        es = reinterpret_cast<const int4*>(ei)[e4];
        ed = reinterpret_cast<const int4*>(ei + N_EDGES)[e4];
        es.x = min(max(es.x, 0), N_NODES - 1);
        es.y = min(max(es.y, 0), N_NODES - 1);
        es.z = min(max(es.z, 0), N_NODES - 1);
        es.w = min(max(es.w, 0), N_NODES - 1);
        ed.x = min(max(ed.x, 0), N_NODES - 1);
        ed.y = min(max(ed.y, 0), N_NODES - 1);
        ed.z = min(max(ed.z, 0), N_NODES - 1);
        ed.w = min(max(ed.w, 0), N_NODES - 1);
        int4 r;
        r.x = atomicAdd(&g_cnt4[0 * N_NODES + ed.x], 1);
        r.y = atomicAdd(&g_cnt4[1 * N_NODES + ed.y], 1);
        r.z = atomicAdd(&g_cnt4[2 * N_NODES + ed.z], 1);
        r.w = atomicAdd(&g_cnt4[3 * N_NODES + ed.w], 1);
        reinterpret_cast<int4*>(g_rank)[e4] = r;
    }
    grid_barrier(2 * BUILD_B);

    // ---- P2a: per-tile inclusive scan of totals (blocks 0..195) ----
    int c0 = 0, c1 = 0, c2 = 0, tot = 0;
    const bool scan_blk = (blockIdx.x < SCAN_B);
    const int gid = blockIdx.x * SCAN_T + tid;   // node id for scan blocks
    if (scan_blk) {
        if (gid < N_NODES) {
            c0 = g_cnt4[gid];
            c1 = g_cnt4[N_NODES + gid];
            c2 = g_cnt4[2 * N_NODES + gid];
            tot = c0 + c1 + c2 + g_cnt4[3 * N_NODES + gid];
            g_cnt[gid] = tot;
        }
        st[tid] = tot;
        __syncthreads();
        #pragma unroll
        for (int o = 1; o < SCAN_T; o <<= 1) {
            int t = (tid >= o) ? st[tid - o] : 0;
            __syncthreads();
            st[tid] += t;
            __syncthreads();
        }
        if (tid == 0) g_bsums[blockIdx.x] = st[SCAN_T - 1];
    }
    grid_barrier(3 * BUILD_B);

    // ---- P2b: scan block sums, write bases (blocks 0..195) ----
    if (scan_blk) {
        int bv = (tid < SCAN_B) ? *(volatile int*)&g_bsums[tid] : 0;
        sb[tid] = bv;
        __syncthreads();
        #pragma unroll
        for (int o = 1; o < SCAN_T; o <<= 1) {
            int t = (tid >= o) ? sb[tid - o] : 0;
            __syncthreads();
            sb[tid] += t;
            __syncthreads();
        }
        const int base = (blockIdx.x > 0) ? sb[blockIdx.x - 1] : 0;
        if (gid < N_NODES) {
            const int excl = base + st[tid] - tot;
            g_base4[gid]               = excl;       // row0 base == CSR row start
            g_base4[N_NODES + gid]     = excl + c0;
            g_base4[2 * N_NODES + gid] = excl + c0 + c1;
            g_base4[3 * N_NODES + gid] = excl + c0 + c1 + c2;
        }
    }
    grid_barrier(4 * BUILD_B);

    // ---- P3: bucket fill (no atomics; base + rank) ----
    if (has_e) {
        int4 r = reinterpret_cast<const int4*>(g_rank)[e4];
        const int p0 = g_base4[0 * N_NODES + ed.x] + r.x;
        const int p1 = g_base4[1 * N_NODES + ed.y] + r.y;
        const int p2 = g_base4[2 * N_NODES + ed.z] + r.z;
        const int p3 = g_base4[3 * N_NODES + ed.w] + r.w;
        g_srcs[p0] = es.x;
        g_srcs[p1] = es.y;
        g_srcs[p2] = es.z;
        g_srcs[p3] = es.w;
    }
}

// -------------------- gather-aggregate: fp16 in, fp16 out ------------------
__device__ __forceinline__ void acc_h2(float4& a, uint2 p) {
    __half2 h0 = *reinterpret_cast<__half2*>(&p.x);
    __half2 h1 = *reinterpret_cast<__half2*>(&p.y);
    float2 f0 = __half22float2(h0);
    float2 f1 = __half22float2(h1);
    a.x += f0.x; a.y += f0.y; a.z += f1.x; a.w += f1.y;
}

__global__ void __launch_bounds__(256, 6)
agg_kernel() {
    // reset the build kernel's grid-barrier counter for the next replay
    // (stream-ordered after build_kernel; safe)
    if (blockIdx.x == 0 && threadIdx.x == 0) g_barrier = 0;

    const int node = (blockIdx.x * blockDim.x + threadIdx.x) >> 5;
    if (node >= N_NODES) return;
    const int lane = threadIdx.x & 31;

    const int start = g_base4[node];   // row0 base == CSR row start
    const int cnt   = g_cnt[node];
    const int end   = start + cnt;

    const uint2* xh2 = reinterpret_cast<const uint2*>(g_xh);

    float4 a0 = make_float4(0.f, 0.f, 0.f, 0.f);
    float4 a1 = make_float4(0.f, 0.f, 0.f, 0.f);

    int e = start;
    for (; e + 7 < end; e += 8) {
        int s0 = g_srcs[e],     s1 = g_srcs[e + 1];
        int s2 = g_srcs[e + 2], s3 = g_srcs[e + 3];
        int s4 = g_srcs[e + 4], s5 = g_srcs[e + 5];
        int s6 = g_srcs[e + 6], s7 = g_srcs[e + 7];
        uint2 p0 = __ldg(&xh2[s0 * 32 + lane]);
        uint2 p1 = __ldg(&xh2[s1 * 32 + lane]);
        uint2 p2 = __ldg(&xh2[s2 * 32 + lane]);
        uint2 p3 = __ldg(&xh2[s3 * 32 + lane]);
        uint2 p4 = __ldg(&xh2[s4 * 32 + lane]);
        uint2 p5 = __ldg(&xh2[s5 * 32 + lane]);
        uint2 p6 = __ldg(&xh2[s6 * 32 + lane]);
        uint2 p7 = __ldg(&xh2[s7 * 32 + lane]);
        acc_h2(a0, p0); acc_h2(a1, p1); acc_h2(a0, p2); acc_h2(a1, p3);
        acc_h2(a0, p4); acc_h2(a1, p5); acc_h2(a0, p6); acc_h2(a1, p7);
    }
    const int rem = end - e;
    if (rem > 0) {
        int idx[7];
        #pragma unroll
        for (int i = 0; i < 7; i++)
            idx[i] = (i < rem) ? g_srcs[e + i] : 0;
        uint2 v[7];
        #pragma unroll
        for (int i = 0; i < 7; i++)
            if (i < rem) v[i] = __ldg(&xh2[idx[i] * 32 + lane]);
        #pragma unroll
        for (int i = 0; i < 7; i++)
            if (i < rem) {
                if (i & 1) acc_h2(a1, v[i]); else acc_h2(a0, v[i]);
            }
    }

    const float inv = 1.0f / fmaxf((float)cnt, 1.0f);
    __half2 h0 = __floats2half2_rn((a0.x + a1.x) * inv, (a0.y + a1.y) * inv);
    __half2 h1 = __floats2half2_rn((a0.z + a1.z) * inv, (a0.w + a1.w) * inv);
    uint2 p;
    p.x = *reinterpret_cast<unsigned*>(&h0);
    p.y = *reinterpret_cast<unsigned*>(&h1);
    reinterpret_cast<uint2*>(g_aggh)[(size_t)node * 32 + lane] = p;
}

// -------------------- tensor-core GEMM (persistent, W in smem) -------------
__global__ void __launch_bounds__(256)
gemm_kernel(float* __restrict__ out, const float* __restrict__ b) {
    __shared__ __half Wsm[OUT_F * W_PAD];   // 34816 B

    const int tid  = threadIdx.x;
    const int warp = tid >> 5;
    const int lane = tid & 31;
    const int q    = lane & 3;
    const int g    = lane >> 2;

    for (int i = tid; i < OUT_F * (IN_F / 4); i += 256) {
        const int n = i >> 5;
        const int c = i & 31;
        uint2 v = reinterpret_cast<const uint2*>(g_wh)[n * 32 + c];
        *reinterpret_cast<uint2*>(&Wsm[n * W_PAD + c * 4]) = v;
    }
    __syncthreads();

    const __half* A = g_aggh;

    for (int tile = blockIdx.x; tile < N_TILES; tile += NUM_SM) {
        const int m0 = tile * TILE_M + warp * 16;
        const int rowLo = min(m0 + g,     N_NODES - 1);
        const int rowHi = min(m0 + g + 8, N_NODES - 1);

        float acc[16][4];
        #pragma unroll
        for (int t = 0; t < 16; t++)
            #pragma unroll
            for (int j = 0; j < 4; j++) acc[t][j] = 0.0f;

        #pragma unroll
        for (int ks = 0; ks < 8; ks++) {
            const int ka = ks * 16 + 2 * q;
            unsigned a0 = *reinterpret_cast<const unsigned*>(&A[(size_t)rowLo * IN_F + ka]);
            unsigned a1 = *reinterpret_cast<const unsigned*>(&A[(size_t)rowHi * IN_F + ka]);
            unsigned a2 = *reinterpret_cast<const unsigned*>(&A[(size_t)rowLo * IN_F + ka + 8]);
            unsigned a3 = *reinterpret_cast<const unsigned*>(&A[(size_t)rowHi * IN_F + ka + 8]);

            #pragma unroll
            for (int t = 0; t < 16; t++) {
                const int n = t * 8 + g;
                unsigned b0 = *reinterpret_cast<const unsigned*>(&Wsm[n * W_PAD + ka]);
                unsigned b1 = *reinterpret_cast<const unsigned*>(&Wsm[n * W_PAD + ka + 8]);
                asm volatile(
                    "mma.sync.aligned.m16n8k16.row.col.f32.f16.f16.f32 "
                    "{%0,%1,%2,%3}, {%4,%5,%6,%7}, {%8,%9}, {%0,%1,%2,%3};"
                    : "+f"(acc[t][0]), "+f"(acc[t][1]), "+f"(acc[t][2]), "+f"(acc[t][3])
                    : "r"(a0), "r"(a1), "r"(a2), "r"(a3), "r"(b0), "r"(b1));
            }
        }

        const int mLo = m0 + g;
        const int mHi = m0 + g + 8;
        #pragma unroll
        for (int t = 0; t < 16; t++) {
            const int col = t * 8 + 2 * q;
            const float b0v = b[col];
            const float b1v = b[col + 1];
            if (mLo < N_NODES) {
                float2 o = make_float2(acc[t][0] + b0v, acc[t][1] + b1v);
                *reinterpret_cast<float2*>(out + (size_t)mLo * OUT_F + col) = o;
            }
            if (mHi < N_NODES) {
                float2 o = make_float2(acc[t][2] + b0v, acc[t][3] + b1v);
                *reinterpret_cast<float2*>(out + (size_t)mHi * OUT_F + col) = o;
            }
        }
    }
}

// ---------------------------------------------------------------------------
extern "C" void kernel_launch(void* const* d_in, const int* in_sizes, int n_in,
                              void* d_out, int out_size) {
    const float* x  = nullptr;
    const int*   ei = nullptr;
    const float* W  = nullptr;
    const float* b  = nullptr;

    for (int i = 0; i < n_in; i++) {
        switch (in_sizes[i]) {
            case N_NODES * IN_F:  x  = (const float*)d_in[i]; break;
            case 2 * N_EDGES:     ei = (const int*)d_in[i];   break;
            case OUT_F * IN_F:    W  = (const float*)d_in[i]; break;
            case OUT_F:           b  = (const float*)d_in[i]; break;
            default: break;
        }
    }

    float* out = (float*)d_out;

    build_kernel<<<BUILD_B, 256>>>(reinterpret_cast<const float4*>(x), W, ei);

    const int agg_blocks = (N_NODES * 32 + 255) / 256;   // 6250
    agg_kernel<<<agg_blocks, 256>>>();

    gemm_kernel<<<NUM_SM, 256>>>(out, b);
}

// round 17
// speedup vs baseline: 1.0797x; 1.0797x over previous
#include <cuda_runtime.h>
#include <cuda_fp16.h>
#include <stdint.h>

#define N_NODES  50000
#define N_EDGES  800000
#define IN_F     128
#define OUT_F    128

#define SCAN_T   256
#define SCAN_B   ((N_NODES + SCAN_T - 1) / SCAN_T)   // 196

#define NUM_SM   148
#define TILE_M   128
#define N_TILES  ((N_NODES + TILE_M - 1) / TILE_M)   // 391

#define W_PAD    136   // W smem row stride in halves (128 + 8 -> bank-conflict-free)

// -------------------- device scratch (no allocation allowed) ---------------
__device__ __align__(16) __half g_xh[N_NODES * IN_F];    // fp16 copy of x
__device__ __align__(16) __half g_aggh[N_NODES * IN_F];  // fp16 normalized h
__device__ __align__(16) __half g_wh[OUT_F * IN_F];      // fp16 copy of W
__device__ int   g_cnt4[4 * N_NODES];   // replicated histograms (stripe = edge%4)
__device__ int   g_base4[4 * N_NODES];  // per-(node,replica) bases; row0 = CSR start
__device__ int   g_cnt[N_NODES];        // per-node totals
__device__ __align__(16) int g_rank[N_EDGES];  // rank within (node,replica)
__device__ int   g_srcs[N_EDGES];       // edge sources grouped by dst
__device__ int   g_bsums[SCAN_B];
__device__ int   g_scan_done;           // grid-barrier counter (reset by hist)

// -------------------- 0) convert x,W -> fp16 AND zero g_cnt4 ---------------
__global__ void __launch_bounds__(256)
convert_kernel(const float4* __restrict__ x4, const float* __restrict__ W) {
    const int gtid   = blockIdx.x * blockDim.x + threadIdx.x;
    const int stride = gridDim.x * blockDim.x;
    uint2* xh2 = reinterpret_cast<uint2*>(g_xh);
    const int n4 = N_NODES * IN_F / 4;   // 1.6M
    for (int i = gtid; i < n4; i += stride) {
        float4 v = x4[i];
        __half2 h0 = __floats2half2_rn(v.x, v.y);
        __half2 h1 = __floats2half2_rn(v.z, v.w);
        uint2 p;
        p.x = *reinterpret_cast<unsigned*>(&h0);
        p.y = *reinterpret_cast<unsigned*>(&h1);
        xh2[i] = p;
    }
    // zero histogram replicas (replaces cudaMemsetAsync)
    int4* cnt4v = reinterpret_cast<int4*>(g_cnt4);
    for (int i = gtid; i < N_NODES; i += stride)   // 4*N_NODES ints = N_NODES int4
        cnt4v[i] = make_int4(0, 0, 0, 0);
    // W: 16384 floats -> 8192 half2
    unsigned* wh2 = reinterpret_cast<unsigned*>(g_wh);
    if (gtid < OUT_F * IN_F / 2) {
        float2 w = reinterpret_cast<const float2*>(W)[gtid];
        __half2 h = __floats2half2_rn(w.x, w.y);
        wh2[gtid] = *reinterpret_cast<unsigned*>(&h);
    }
}

// -------------------- 1) histogram (replicated) + rank capture -------------
__global__ void __launch_bounds__(256)
hist_kernel(const int* __restrict__ ei) {
    const int gtid = blockIdx.x * blockDim.x + threadIdx.x;
    if (gtid == 0) g_scan_done = 0;   // reset grid barrier for scan kernel
    const int e4 = gtid;
    if (e4 >= N_EDGES / 4) return;
    int4 d = reinterpret_cast<const int4*>(ei + N_EDGES)[e4];
    d.x = min(max(d.x, 0), N_NODES - 1);
    d.y = min(max(d.y, 0), N_NODES - 1);
    d.z = min(max(d.z, 0), N_NODES - 1);
    d.w = min(max(d.w, 0), N_NODES - 1);
    int4 r;
    r.x = atomicAdd(&g_cnt4[0 * N_NODES + d.x], 1);
    r.y = atomicAdd(&g_cnt4[1 * N_NODES + d.y], 1);
    r.z = atomicAdd(&g_cnt4[2 * N_NODES + d.z], 1);
    r.w = atomicAdd(&g_cnt4[3 * N_NODES + d.w], 1);
    reinterpret_cast<int4*>(g_rank)[e4] = r;
}

// -------------------- 2) fused exclusive scan (single kernel) --------------
__global__ void __launch_bounds__(SCAN_T)
scan_fused_kernel() {
    __shared__ int st[SCAN_T];
    __shared__ int sb[SCAN_T];
    const int tid = threadIdx.x;
    const int gid = blockIdx.x * SCAN_T + tid;

    int c0 = 0, c1 = 0, c2 = 0, tot = 0;
    if (gid < N_NODES) {
        c0 = g_cnt4[gid];
        c1 = g_cnt4[N_NODES + gid];
        c2 = g_cnt4[2 * N_NODES + gid];
        tot = c0 + c1 + c2 + g_cnt4[3 * N_NODES + gid];
        g_cnt[gid] = tot;
    }
    st[tid] = tot;
    __syncthreads();
    #pragma unroll
    for (int o = 1; o < SCAN_T; o <<= 1) {
        int t = (tid >= o) ? st[tid - o] : 0;
        __syncthreads();
        st[tid] += t;
        __syncthreads();
    }

    if (tid == 0) {
        g_bsums[blockIdx.x] = st[SCAN_T - 1];
        __threadfence();
        atomicAdd(&g_scan_done, 1);
    }
    if (tid == 0) {
        int v;
        do {
            asm volatile("ld.global.acquire.gpu.b32 %0, [%1];"
                         : "=r"(v) : "l"(&g_scan_done));
        } while (v < (int)gridDim.x);
    }
    __syncthreads();

    int bv = (tid < SCAN_B) ? *(volatile int*)&g_bsums[tid] : 0;
    sb[tid] = bv;
    __syncthreads();
    #pragma unroll
    for (int o = 1; o < SCAN_T; o <<= 1) {
        int t = (tid >= o) ? sb[tid - o] : 0;
        __syncthreads();
        sb[tid] += t;
        __syncthreads();
    }
    const int base = (blockIdx.x > 0) ? sb[blockIdx.x - 1] : 0;

    if (gid < N_NODES) {
        const int excl = base + st[tid] - tot;
        g_base4[gid]               = excl;       // row0 base == CSR row start
        g_base4[N_NODES + gid]     = excl + c0;
        g_base4[2 * N_NODES + gid] = excl + c0 + c1;
        g_base4[3 * N_NODES + gid] = excl + c0 + c1 + c2;
    }
}

// -------------------- 3) bucket-fill: NO atomics (base + rank) -------------
__global__ void fill_kernel(const int* __restrict__ ei) {
    const int e4 = blockIdx.x * blockDim.x + threadIdx.x;
    if (e4 >= N_EDGES / 4) return;
    int4 s = reinterpret_cast<const int4*>(ei)[e4];
    int4 d = reinterpret_cast<const int4*>(ei + N_EDGES)[e4];
    int4 r = reinterpret_cast<const int4*>(g_rank)[e4];
    s.x = min(max(s.x, 0), N_NODES - 1);
    s.y = min(max(s.y, 0), N_NODES - 1);
    s.z = min(max(s.z, 0), N_NODES - 1);
    s.w = min(max(s.w, 0), N_NODES - 1);
    d.x = min(max(d.x, 0), N_NODES - 1);
    d.y = min(max(d.y, 0), N_NODES - 1);
    d.z = min(max(d.z, 0), N_NODES - 1);
    d.w = min(max(d.w, 0), N_NODES - 1);
    const int p0 = g_base4[0 * N_NODES + d.x] + r.x;
    const int p1 = g_base4[1 * N_NODES + d.y] + r.y;
    const int p2 = g_base4[2 * N_NODES + d.z] + r.z;
    const int p3 = g_base4[3 * N_NODES + d.w] + r.w;
    g_srcs[p0] = s.x;
    g_srcs[p1] = s.y;
    g_srcs[p2] = s.z;
    g_srcs[p3] = s.w;
}

// -------------------- 4) gather-aggregate: fp16 in, fp16 out ---------------
__device__ __forceinline__ void acc_h2(float4& a, uint2 p) {
    __half2 h0 = *reinterpret_cast<__half2*>(&p.x);
    __half2 h1 = *reinterpret_cast<__half2*>(&p.y);
    float2 f0 = __half22float2(h0);
    float2 f1 = __half22float2(h1);
    a.x += f0.x; a.y += f0.y; a.z += f1.x; a.w += f1.y;
}

__global__ void __launch_bounds__(256, 6)
agg_kernel() {
    const int node = (blockIdx.x * blockDim.x + threadIdx.x) >> 5;
    if (node >= N_NODES) return;
    const int lane = threadIdx.x & 31;

    const int start = g_base4[node];   // row0 base == CSR row start
    const int cnt   = g_cnt[node];
    const int end   = start + cnt;

    const uint2* xh2 = reinterpret_cast<const uint2*>(g_xh);

    float4 a0 = make_float4(0.f, 0.f, 0.f, 0.f);
    float4 a1 = make_float4(0.f, 0.f, 0.f, 0.f);

    int e = start;
    for (; e + 7 < end; e += 8) {
        int s0 = g_srcs[e],     s1 = g_srcs[e + 1];
        int s2 = g_srcs[e + 2], s3 = g_srcs[e + 3];
        int s4 = g_srcs[e + 4], s5 = g_srcs[e + 5];
        int s6 = g_srcs[e + 6], s7 = g_srcs[e + 7];
        uint2 p0 = __ldg(&xh2[s0 * 32 + lane]);
        uint2 p1 = __ldg(&xh2[s1 * 32 + lane]);
        uint2 p2 = __ldg(&xh2[s2 * 32 + lane]);
        uint2 p3 = __ldg(&xh2[s3 * 32 + lane]);
        uint2 p4 = __ldg(&xh2[s4 * 32 + lane]);
        uint2 p5 = __ldg(&xh2[s5 * 32 + lane]);
        uint2 p6 = __ldg(&xh2[s6 * 32 + lane]);
        uint2 p7 = __ldg(&xh2[s7 * 32 + lane]);
        acc_h2(a0, p0); acc_h2(a1, p1); acc_h2(a0, p2); acc_h2(a1, p3);
        acc_h2(a0, p4); acc_h2(a1, p5); acc_h2(a0, p6); acc_h2(a1, p7);
    }
    const int rem = end - e;
    if (rem > 0) {
        int idx[7];
        #pragma unroll
        for (int i = 0; i < 7; i++)
            idx[i] = (i < rem) ? g_srcs[e + i] : 0;
        uint2 v[7];
        #pragma unroll
        for (int i = 0; i < 7; i++)
            if (i < rem) v[i] = __ldg(&xh2[idx[i] * 32 + lane]);
        #pragma unroll
        for (int i = 0; i < 7; i++)
            if (i < rem) {
                if (i & 1) acc_h2(a1, v[i]); else acc_h2(a0, v[i]);
            }
    }

    const float inv = 1.0f / fmaxf((float)cnt, 1.0f);
    __half2 h0 = __floats2half2_rn((a0.x + a1.x) * inv, (a0.y + a1.y) * inv);
    __half2 h1 = __floats2half2_rn((a0.z + a1.z) * inv, (a0.w + a1.w) * inv);
    uint2 p;
    p.x = *reinterpret_cast<unsigned*>(&h0);
    p.y = *reinterpret_cast<unsigned*>(&h1);
    reinterpret_cast<uint2*>(g_aggh)[(size_t)node * 32 + lane] = p;
}

// -------------------- 5) tensor-core GEMM (persistent, W in smem) ----------
// HMMA m16n8k16 fp16->fp32. 148 persistent blocks; W staged into smem ONCE
// per block (padded rows: stride W_PAD halves -> B-frag LDS is conflict-free).
// A fragments from global (L2-resident).
__global__ void __launch_bounds__(256)
gemm_kernel(float* __restrict__ out, const float* __restrict__ b) {
    __shared__ __half Wsm[OUT_F * W_PAD];   // 128*136*2 = 34816 B

    const int tid  = threadIdx.x;
    const int warp = tid >> 5;
    const int lane = tid & 31;
    const int q    = lane & 3;
    const int g    = lane >> 2;

    // stage W: Wsm[n][k] = g_wh[n*128 + k], row stride W_PAD
    for (int i = tid; i < OUT_F * (IN_F / 4); i += 256) {
        const int n = i >> 5;           // 32 uint2 per row
        const int c = i & 31;           // uint2 index within row
        uint2 v = reinterpret_cast<const uint2*>(g_wh)[n * 32 + c];
        *reinterpret_cast<uint2*>(&Wsm[n * W_PAD + c * 4]) = v;
    }
    __syncthreads();

    const __half* A = g_aggh;

    for (int tile = blockIdx.x; tile < N_TILES; tile += NUM_SM) {
        const int m0 = tile * TILE_M + warp * 16;
        const int rowLo = min(m0 + g,     N_NODES - 1);
        const int rowHi = min(m0 + g + 8, N_NODES - 1);

        float acc[16][4];
        #pragma unroll
        for (int t = 0; t < 16; t++)
            #pragma unroll
            for (int j = 0; j < 4; j++) acc[t][j] = 0.0f;

        #pragma unroll
        for (int ks = 0; ks < 8; ks++) {
            const int ka = ks * 16 + 2 * q;
            unsigned a0 = *reinterpret_cast<const unsigned*>(&A[(size_t)rowLo * IN_F + ka]);
            unsigned a1 = *reinterpret_cast<const unsigned*>(&A[(size_t)rowHi * IN_F + ka]);
            unsigned a2 = *reinterpret_cast<const unsigned*>(&A[(size_t)rowLo * IN_F + ka + 8]);
            unsigned a3 = *reinterpret_cast<const unsigned*>(&A[(size_t)rowHi * IN_F + ka + 8]);

            #pragma unroll
            for (int t = 0; t < 16; t++) {
                const int n = t * 8 + g;
                unsigned b0 = *reinterpret_cast<const unsigned*>(&Wsm[n * W_PAD + ka]);
                unsigned b1 = *reinterpret_cast<const unsigned*>(&Wsm[n * W_PAD + ka + 8]);
                asm volatile(
                    "mma.sync.aligned.m16n8k16.row.col.f32.f16.f16.f32 "
                    "{%0,%1,%2,%3}, {%4,%5,%6,%7}, {%8,%9}, {%0,%1,%2,%3};"
                    : "+f"(acc[t][0]), "+f"(acc[t][1]), "+f"(acc[t][2]), "+f"(acc[t][3])
                    : "r"(a0), "r"(a1), "r"(a2), "r"(a3), "r"(b0), "r"(b1));
            }
        }

        const int mLo = m0 + g;
        const int mHi = m0 + g + 8;
        #pragma unroll
        for (int t = 0; t < 16; t++) {
            const int col = t * 8 + 2 * q;
            const float b0v = b[col];
            const float b1v = b[col + 1];
            if (mLo < N_NODES) {
                float2 o = make_float2(acc[t][0] + b0v, acc[t][1] + b1v);
                *reinterpret_cast<float2*>(out + (size_t)mLo * OUT_F + col) = o;
            }
            if (mHi < N_NODES) {
                float2 o = make_float2(acc[t][2] + b0v, acc[t][3] + b1v);
                *reinterpret_cast<float2*>(out + (size_t)mHi * OUT_F + col) = o;
            }
        }
    }
}

// ---------------------------------------------------------------------------
extern "C" void kernel_launch(void* const* d_in, const int* in_sizes, int n_in,
                              void* d_out, int out_size) {
    const float* x  = nullptr;
    const int*   ei = nullptr;
    const float* W  = nullptr;
    const float* b  = nullptr;

    for (int i = 0; i < n_in; i++) {
        switch (in_sizes[i]) {
            case N_NODES * IN_F:  x  = (const float*)d_in[i]; break;
            case 2 * N_EDGES:     ei = (const int*)d_in[i];   break;
            case OUT_F * IN_F:    W  = (const float*)d_in[i]; break;
            case OUT_F:           b  = (const float*)d_in[i]; break;
            default: break;
        }
    }

    float* out = (float*)d_out;

    convert_kernel<<<2048, 256>>>(reinterpret_cast<const float4*>(x), W);
    hist_kernel<<<(N_EDGES / 4 + 255) / 256, 256>>>(ei);
    scan_fused_kernel<<<SCAN_B, SCAN_T>>>();
    fill_kernel<<<(N_EDGES / 4 + 255) / 256, 256>>>(ei);

    const int agg_blocks = (N_NODES * 32 + 255) / 256;   // 6250
    agg_kernel<<<agg_blocks, 256>>>();

    gemm_kernel<<<NUM_SM, 256>>>(out, b);
}